// round 2
// baseline (speedup 1.0000x reference)
#include <cuda_runtime.h>
#include <cuda_bf16.h>

// Contrastive loss, fused single kernel:
//   per pair p: a = emb[pair_a[p]], b = emb[pair_b[p]]  (rows of D=512 floats)
//   sq = ||a||^2 + ||b||^2 - 2 a.b ; d = sqrt(max(sq,1e-12))
//   loss_p = (1-i)*max(0, m-d)^2 + i*d^2,  m = 1.0
//   out = sum_p loss_p / (P + 1e-10)
//
// Warp-per-pair float4 gather (128B coalesced, MLP=8), shuffle reduce,
// per-block partial to __device__ array, LAST finishing block performs the
// deterministic final tree-sum (fixed index order) and writes out.
// Counter uses atomicInc with wrap so it self-resets for graph replays.

#define D_DIM 512
#define VEC_PER_ROW (D_DIM / 4)      // 128 float4 per row
#define WARPS_PER_BLOCK 8
#define THREADS_PER_BLOCK (WARPS_PER_BLOCK * 32)
#define MAX_BLOCKS 16384

__device__ float        g_partials[MAX_BLOCKS];
__device__ unsigned int g_counter = 0;

__global__ __launch_bounds__(THREADS_PER_BLOCK)
void contrastive_fused_kernel(const float* __restrict__ emb,
                              const int* __restrict__ pair_a,
                              const int* __restrict__ pair_b,
                              const int* __restrict__ pair_same,
                              float* __restrict__ out,
                              int P)
{
    const int warp_id = threadIdx.x >> 5;
    const int lane    = threadIdx.x & 31;
    const int p       = blockIdx.x * WARPS_PER_BLOCK + warp_id;

    float loss = 0.0f;

    if (p < P) {
        const int ia = pair_a[p];
        const int ib = pair_b[p];
        const float4* __restrict__ ra =
            reinterpret_cast<const float4*>(emb) + (size_t)ia * VEC_PER_ROW;
        const float4* __restrict__ rb =
            reinterpret_cast<const float4*>(emb) + (size_t)ib * VEC_PER_ROW;

        float saa = 0.0f, sbb = 0.0f, sab = 0.0f;

        // 128 float4 per row / 32 lanes = 4 iterations; all 8 loads issued
        // back-to-back (independent) for MLP=8.
        float4 va[4], vb[4];
        #pragma unroll
        for (int k = 0; k < 4; ++k) {
            va[k] = __ldg(ra + lane + k * 32);
            vb[k] = __ldg(rb + lane + k * 32);
        }
        #pragma unroll
        for (int k = 0; k < 4; ++k) {
            saa += va[k].x * va[k].x + va[k].y * va[k].y
                 + va[k].z * va[k].z + va[k].w * va[k].w;
            sbb += vb[k].x * vb[k].x + vb[k].y * vb[k].y
                 + vb[k].z * vb[k].z + vb[k].w * vb[k].w;
            sab += va[k].x * vb[k].x + va[k].y * vb[k].y
                 + va[k].z * vb[k].z + va[k].w * vb[k].w;
        }

        // Warp tree reduction of the three sums.
        #pragma unroll
        for (int off = 16; off > 0; off >>= 1) {
            saa += __shfl_xor_sync(0xFFFFFFFFu, saa, off);
            sbb += __shfl_xor_sync(0xFFFFFFFFu, sbb, off);
            sab += __shfl_xor_sync(0xFFFFFFFFu, sab, off);
        }

        if (lane == 0) {
            float sq = saa + sbb - 2.0f * sab;
            sq = fmaxf(sq, 1e-12f);
            float d = sqrtf(sq);
            float i = (float)pair_same[p];
            float h = fmaxf(0.0f, 1.0f - d);
            loss = (1.0f - i) * h * h + i * d * d;
        }
    }

    // Block reduction of per-warp losses.
    __shared__ float s_loss[WARPS_PER_BLOCK];
    __shared__ bool  s_is_last;
    if (lane == 0) s_loss[warp_id] = loss;
    __syncthreads();

    if (threadIdx.x == 0) {
        float acc = 0.0f;
        #pragma unroll
        for (int w = 0; w < WARPS_PER_BLOCK; ++w) acc += s_loss[w];
        g_partials[blockIdx.x] = acc;
        __threadfence();  // make partial visible before signaling
        // atomicInc wraps to 0 after gridDim.x increments -> self-resetting
        // across graph replays. Old value == gridDim.x-1 identifies the last
        // block to finish.
        unsigned int prev = atomicInc(&g_counter, gridDim.x - 1);
        s_is_last = (prev == gridDim.x - 1);
    }
    __syncthreads();

    // Last block: deterministic final reduction in fixed index order.
    if (s_is_last) {
        __shared__ float s_fin[THREADS_PER_BLOCK];
        float acc = 0.0f;
        for (int i = threadIdx.x; i < (int)gridDim.x; i += THREADS_PER_BLOCK)
            acc += g_partials[i];
        s_fin[threadIdx.x] = acc;
        __syncthreads();
        #pragma unroll
        for (int off = THREADS_PER_BLOCK / 2; off > 0; off >>= 1) {
            if (threadIdx.x < off) s_fin[threadIdx.x] += s_fin[threadIdx.x + off];
            __syncthreads();
        }
        if (threadIdx.x == 0)
            out[0] = s_fin[0] / ((float)P + 1e-10f);
    }
}

extern "C" void kernel_launch(void* const* d_in, const int* in_sizes, int n_in,
                              void* d_out, int out_size)
{
    const float* emb       = (const float*)d_in[0];
    const int*   pair_a    = (const int*)d_in[1];
    const int*   pair_b    = (const int*)d_in[2];
    const int*   pair_same = (const int*)d_in[3];
    float*       out       = (float*)d_out;

    const int P = in_sizes[1];  // element count of pair_a
    int num_blocks = (P + WARPS_PER_BLOCK - 1) / WARPS_PER_BLOCK;
    if (num_blocks > MAX_BLOCKS) num_blocks = MAX_BLOCKS;  // P=32768 -> 4096

    contrastive_fused_kernel<<<num_blocks, THREADS_PER_BLOCK>>>(
        emb, pair_a, pair_b, pair_same, out, P);
}

// round 4
// speedup vs baseline: 1.2426x; 1.2426x over previous
#include <cuda_runtime.h>
#include <cuda_bf16.h>

// Contrastive loss, fused single kernel (v2 sync, resubmit after infra fail):
//   per pair p: a = emb[pair_a[p]], b = emb[pair_b[p]]  (rows of D=512 floats)
//   sq = ||a-b||^2  (== ||a||^2+||b||^2-2a.b) ; d = sqrt(max(sq,1e-12))
//   loss_p = (1-i)*max(0, 1-d)^2 + i*d^2
//   out = sum_p loss_p / (P + 1e-10)
//
// Changes vs v1 fused:
//  - acq_rel atomic ticket (no membar.gl -> no CCTL.IVALL L1 flush per block)
//  - 2048 blocks x 2 pairs/warp (half the atomics, half the tail read)
//  - ||a-b||^2 form: 1 accumulator, 5 shuffles/pair instead of 15
//  - counter self-reset via atomicExch (replay-safe)

#define D_DIM 512
#define VEC_PER_ROW (D_DIM / 4)      // 128 float4 per row
#define WARPS_PER_BLOCK 8
#define THREADS_PER_BLOCK (WARPS_PER_BLOCK * 32)
#define PAIRS_PER_WARP 2
#define MAX_BLOCKS 16384

__device__ float        g_partials[MAX_BLOCKS];
__device__ unsigned int g_counter = 0;

// Ticket atomic with acq_rel semantics: release orders the preceding partial
// store (no full fence / no L1 flush); acquire orders the last block's
// subsequent partial reads.
__device__ __forceinline__ unsigned int atom_add_acqrel(unsigned int* p,
                                                        unsigned int v) {
    unsigned int old;
    asm volatile("atom.acq_rel.gpu.global.add.u32 %0, [%1], %2;"
                 : "=r"(old) : "l"(p), "r"(v) : "memory");
    return old;
}

__global__ __launch_bounds__(THREADS_PER_BLOCK)
void contrastive_fused_kernel(const float* __restrict__ emb,
                              const int* __restrict__ pair_a,
                              const int* __restrict__ pair_b,
                              const int* __restrict__ pair_same,
                              float* __restrict__ out,
                              int P)
{
    const int warp_id     = threadIdx.x >> 5;
    const int lane        = threadIdx.x & 31;
    const int warp_global = blockIdx.x * WARPS_PER_BLOCK + warp_id;
    const int warp_stride = gridDim.x * WARPS_PER_BLOCK;

    float warp_loss = 0.0f;   // meaningful on lane 0 only

    #pragma unroll
    for (int j = 0; j < PAIRS_PER_WARP; ++j) {
        const int p = warp_global + j * warp_stride;
        if (p < P) {
            const int ia = pair_a[p];
            const int ib = pair_b[p];
            const float4* __restrict__ ra =
                reinterpret_cast<const float4*>(emb) + (size_t)ia * VEC_PER_ROW;
            const float4* __restrict__ rb =
                reinterpret_cast<const float4*>(emb) + (size_t)ib * VEC_PER_ROW;

            // 8 independent 16B loads (MLP=8, 512B/warp each, fully coalesced)
            float4 va[4], vb[4];
            #pragma unroll
            for (int k = 0; k < 4; ++k) {
                va[k] = __ldg(ra + lane + k * 32);
                vb[k] = __ldg(rb + lane + k * 32);
            }

            // ||a-b||^2 per lane: 1 accumulator
            float s = 0.0f;
            #pragma unroll
            for (int k = 0; k < 4; ++k) {
                float dx = va[k].x - vb[k].x;
                float dy = va[k].y - vb[k].y;
                float dz = va[k].z - vb[k].z;
                float dw = va[k].w - vb[k].w;
                s += dx * dx + dy * dy + dz * dz + dw * dw;
            }

            // Single warp tree reduction (5 shfl)
            #pragma unroll
            for (int off = 16; off > 0; off >>= 1)
                s += __shfl_xor_sync(0xFFFFFFFFu, s, off);

            if (lane == 0) {
                float sq = fmaxf(s, 1e-12f);
                float d = sqrtf(sq);
                float i = (float)pair_same[p];
                float h = fmaxf(0.0f, 1.0f - d);
                warp_loss += (1.0f - i) * h * h + i * d * d;
            }
        }
    }

    // Block reduction of per-warp losses.
    __shared__ float s_loss[WARPS_PER_BLOCK];
    __shared__ bool  s_is_last;
    if (lane == 0) s_loss[warp_id] = warp_loss;
    __syncthreads();

    if (threadIdx.x == 0) {
        float acc = 0.0f;
        #pragma unroll
        for (int w = 0; w < WARPS_PER_BLOCK; ++w) acc += s_loss[w];
        g_partials[blockIdx.x] = acc;          // st.global (write-through to L2)
        unsigned int prev = atom_add_acqrel(&g_counter, 1u);  // release-orders store
        s_is_last = (prev == gridDim.x - 1);
        if (s_is_last) atomicExch(&g_counter, 0u);  // replay-safe self-reset
    }
    __syncthreads();

    // Last block: deterministic final reduction in fixed index order.
    if (s_is_last) {
        __shared__ float s_fin[THREADS_PER_BLOCK];
        float acc = 0.0f;
        for (int i = threadIdx.x; i < (int)gridDim.x; i += THREADS_PER_BLOCK)
            acc += g_partials[i];
        s_fin[threadIdx.x] = acc;
        __syncthreads();
        #pragma unroll
        for (int off = THREADS_PER_BLOCK / 2; off > 0; off >>= 1) {
            if (threadIdx.x < off) s_fin[threadIdx.x] += s_fin[threadIdx.x + off];
            __syncthreads();
        }
        if (threadIdx.x == 0)
            out[0] = s_fin[0] / ((float)P + 1e-10f);
    }
}

extern "C" void kernel_launch(void* const* d_in, const int* in_sizes, int n_in,
                              void* d_out, int out_size)
{
    const float* emb       = (const float*)d_in[0];
    const int*   pair_a    = (const int*)d_in[1];
    const int*   pair_b    = (const int*)d_in[2];
    const int*   pair_same = (const int*)d_in[3];
    float*       out       = (float*)d_out;

    const int P = in_sizes[1];  // element count of pair_a
    const int pairs_per_block = WARPS_PER_BLOCK * PAIRS_PER_WARP;
    int num_blocks = (P + pairs_per_block - 1) / pairs_per_block;
    if (num_blocks > MAX_BLOCKS) num_blocks = MAX_BLOCKS;  // P=32768 -> 2048

    contrastive_fused_kernel<<<num_blocks, THREADS_PER_BLOCK>>>(
        emb, pair_a, pair_b, pair_same, out, P);
}

// round 5
// speedup vs baseline: 1.3949x; 1.1226x over previous
#include <cuda_runtime.h>
#include <cuda_bf16.h>

// Contrastive loss, fused single kernel v3:
//   per pair p: a = emb[pair_a[p]], b = emb[pair_b[p]]  (rows of D=512 floats)
//   sq = ||a-b||^2 ; d = sqrt(max(sq,1e-12))
//   loss_p = (1-i)*max(0, 1-d)^2 + i*d^2 ; out = sum / (P + 1e-10)
//
// v3 vs v2:
//  - __ldcg (L2-only) row loads: zero L1 reuse exists, skip L1 allocation to
//    relieve the L1tex wavefront queue (cross-CTA spread mitigation)
//  - single-wave balanced grid: 1024 blocks x 8 warps x exactly 4 pairs/warp
//  - index prefetch pipeline: next pair's indices load during current compute

#define D_DIM 512
#define VEC_PER_ROW (D_DIM / 4)      // 128 float4 per row
#define WARPS_PER_BLOCK 8
#define THREADS_PER_BLOCK (WARPS_PER_BLOCK * 32)
#define BLOCKS_TARGET 1024           // 8192 warps -> 4 pairs/warp at P=32768
#define MAX_BLOCKS 16384

__device__ float        g_partials[MAX_BLOCKS];
__device__ unsigned int g_counter = 0;

__device__ __forceinline__ unsigned int atom_add_acqrel(unsigned int* p,
                                                        unsigned int v) {
    unsigned int old;
    asm volatile("atom.acq_rel.gpu.global.add.u32 %0, [%1], %2;"
                 : "=r"(old) : "l"(p), "r"(v) : "memory");
    return old;
}

__global__ __launch_bounds__(THREADS_PER_BLOCK)
void contrastive_fused_kernel(const float* __restrict__ emb,
                              const int* __restrict__ pair_a,
                              const int* __restrict__ pair_b,
                              const int* __restrict__ pair_same,
                              float* __restrict__ out,
                              int P)
{
    const int warp_id     = threadIdx.x >> 5;
    const int lane        = threadIdx.x & 31;
    const int warp_global = blockIdx.x * WARPS_PER_BLOCK + warp_id;
    const int warp_stride = gridDim.x * WARPS_PER_BLOCK;

    const float4* __restrict__ embv = reinterpret_cast<const float4*>(emb);

    float warp_loss = 0.0f;   // meaningful on lane 0 only

    int p  = warp_global;
    int ia = 0, ib = 0;
    if (p < P) { ia = __ldg(pair_a + p); ib = __ldg(pair_b + p); }

    while (p < P) {
        // Prefetch next pair's indices (hides idx->row dependent chain).
        const int p_next = p + warp_stride;
        int ia_next = 0, ib_next = 0;
        if (p_next < P) {
            ia_next = __ldg(pair_a + p_next);
            ib_next = __ldg(pair_b + p_next);
        }

        const float4* __restrict__ ra = embv + (size_t)ia * VEC_PER_ROW;
        const float4* __restrict__ rb = embv + (size_t)ib * VEC_PER_ROW;

        // 8 independent 16B L2-only loads (512B/warp each, fully coalesced).
        float4 va[4], vb[4];
        #pragma unroll
        for (int k = 0; k < 4; ++k) {
            va[k] = __ldcg(ra + lane + k * 32);
            vb[k] = __ldcg(rb + lane + k * 32);
        }

        // ||a-b||^2 per lane.
        float s = 0.0f;
        #pragma unroll
        for (int k = 0; k < 4; ++k) {
            float dx = va[k].x - vb[k].x;
            float dy = va[k].y - vb[k].y;
            float dz = va[k].z - vb[k].z;
            float dw = va[k].w - vb[k].w;
            s += dx * dx + dy * dy + dz * dz + dw * dw;
        }

        // Warp tree reduction (5 shfl).
        #pragma unroll
        for (int off = 16; off > 0; off >>= 1)
            s += __shfl_xor_sync(0xFFFFFFFFu, s, off);

        if (lane == 0) {
            float sq = fmaxf(s, 1e-12f);
            float d = sqrtf(sq);
            float i = (float)__ldg(pair_same + p);
            float h = fmaxf(0.0f, 1.0f - d);
            warp_loss += (1.0f - i) * h * h + i * d * d;
        }

        p  = p_next;
        ia = ia_next;
        ib = ib_next;
    }

    // Block reduction of per-warp losses.
    __shared__ float s_loss[WARPS_PER_BLOCK];
    __shared__ bool  s_is_last;
    if (lane == 0) s_loss[warp_id] = warp_loss;
    __syncthreads();

    if (threadIdx.x == 0) {
        float acc = 0.0f;
        #pragma unroll
        for (int w = 0; w < WARPS_PER_BLOCK; ++w) acc += s_loss[w];
        g_partials[blockIdx.x] = acc;
        unsigned int prev = atom_add_acqrel(&g_counter, 1u);  // release-orders store
        s_is_last = (prev == gridDim.x - 1);
        if (s_is_last) atomicExch(&g_counter, 0u);  // replay-safe self-reset
    }
    __syncthreads();

    // Last block: deterministic final reduction in fixed index order.
    if (s_is_last) {
        __shared__ float s_fin[THREADS_PER_BLOCK];
        float acc = 0.0f;
        for (int i = threadIdx.x; i < (int)gridDim.x; i += THREADS_PER_BLOCK)
            acc += g_partials[i];
        s_fin[threadIdx.x] = acc;
        __syncthreads();
        #pragma unroll
        for (int off = THREADS_PER_BLOCK / 2; off > 0; off >>= 1) {
            if (threadIdx.x < off) s_fin[threadIdx.x] += s_fin[threadIdx.x + off];
            __syncthreads();
        }
        if (threadIdx.x == 0)
            out[0] = s_fin[0] / ((float)P + 1e-10f);
    }
}

extern "C" void kernel_launch(void* const* d_in, const int* in_sizes, int n_in,
                              void* d_out, int out_size)
{
    const float* emb       = (const float*)d_in[0];
    const int*   pair_a    = (const int*)d_in[1];
    const int*   pair_b    = (const int*)d_in[2];
    const int*   pair_same = (const int*)d_in[3];
    float*       out       = (float*)d_out;

    const int P = in_sizes[1];  // element count of pair_a

    // Single balanced wave: at P=32768 -> 1024 blocks, exactly 4 pairs/warp.
    int warps_needed = (P + 3) / 4;  // target ~4 pairs per warp
    int num_blocks = (warps_needed + WARPS_PER_BLOCK - 1) / WARPS_PER_BLOCK;
    if (num_blocks > BLOCKS_TARGET) num_blocks = BLOCKS_TARGET;
    if (num_blocks < 1) num_blocks = 1;

    contrastive_fused_kernel<<<num_blocks, THREADS_PER_BLOCK>>>(
        emb, pair_a, pair_b, pair_same, out, P);
}